// round 14
// baseline (speedup 1.0000x reference)
#include <cuda_runtime.h>
#include <cuda_bf16.h>
#include <cstdint>

// Problem constants
#define Bn 32
#define Ln 256
#define Dn 256
#define Hn 256
#define En 8
#define NLn 4
#define Kc 4
#define MROWS (Bn*En*Ln)     // 65536

#define SSTRIDE 264          // bf16 elems per smem row (pad: stride%32banks=4)

__device__ __forceinline__ float fast_tanh(float x)
{
    float y;
    asm("tanh.approx.f32 %0, %1;" : "=f"(y) : "f"(x));
    return y;
}

__device__ __forceinline__ uint32_t s2u(const void* p)
{
    uint32_t a;
    asm("{ .reg .u64 t; cvta.to.shared.u64 t, %1; cvt.u32.u64 %0, t; }"
        : "=r"(a) : "l"(p));
    return a;
}

// pack two fp32 -> bf16x2 (lo in low half)
__device__ __forceinline__ unsigned int pbf2(float lo, float hi)
{
    unsigned int r;
    asm("cvt.rn.bf16x2.f32 %0, %1, %2;" : "=r"(r) : "f"(hi), "f"(lo));
    return r;
}

#define MMA_BF16(c, a, b) \
    asm volatile( \
        "mma.sync.aligned.m16n8k16.row.col.f32.bf16.bf16.f32 " \
        "{%0,%1,%2,%3}, {%4,%5,%6,%7}, {%8,%9}, {%0,%1,%2,%3};" \
        : "+f"((c)[0]), "+f"((c)[1]), "+f"((c)[2]), "+f"((c)[3]) \
        : "r"((a)[0]), "r"((a)[1]), "r"((a)[2]), "r"((a)[3]), \
          "r"((b)[0]), "r"((b)[1]))

// Scratch (device globals - no allocation allowed)
__device__ float g_ln[Bn*Ln*Dn];                 // 8 MB
__device__ float g_u[Bn*Ln*Dn];                  // 8 MB
__device__ float g_y[(size_t)Bn*En*Ln*Hn];       // 64 MB
__device__ float g_pre[(size_t)Bn*En*Ln*Hn];     // 64 MB

// ---------------------------------------------------------------------------
// LayerNorm
// ---------------------------------------------------------------------------
__global__ void ln_kernel(const float* __restrict__ x, const float* __restrict__ g,
                          const float* __restrict__ bb, float* __restrict__ out)
{
    int token = blockIdx.x;
    int t = threadIdx.x;
    __shared__ float red[8];
    __shared__ float meanv, rstdv;

    float v = x[(size_t)token * Dn + t];

    float s = v;
    #pragma unroll
    for (int o = 16; o > 0; o >>= 1) s += __shfl_xor_sync(0xffffffffu, s, o);
    if ((t & 31) == 0) red[t >> 5] = s;
    __syncthreads();
    if (t == 0) {
        float m = 0.f;
        #pragma unroll
        for (int i = 0; i < 8; i++) m += red[i];
        meanv = m * (1.0f / Dn);
    }
    __syncthreads();

    float d = v - meanv;
    float sq = d * d;
    #pragma unroll
    for (int o = 16; o > 0; o >>= 1) sq += __shfl_xor_sync(0xffffffffu, sq, o);
    if ((t & 31) == 0) red[t >> 5] = sq;
    __syncthreads();
    if (t == 0) {
        float vv = 0.f;
        #pragma unroll
        for (int i = 0; i < 8; i++) vv += red[i];
        rstdv = rsqrtf(vv * (1.0f / Dn) + 1e-5f);
    }
    __syncthreads();

    out[(size_t)token * Dn + t] = d * rstdv * g[t] + bb[t];
}

// ---------------------------------------------------------------------------
// Depthwise causal conv1d (K=4, left pad 3) + bias
// ---------------------------------------------------------------------------
__global__ void conv_kernel(const float* __restrict__ ln, const float* __restrict__ cw,
                            const float* __restrict__ cb, float* __restrict__ u)
{
    int idx = blockIdx.x * 256 + threadIdx.x;
    int d  = idx & 255;
    int l  = (idx >> 8) & 255;
    int b0 = idx >> 16;
    float acc = cb[d];
    #pragma unroll
    for (int j = 0; j < Kc; j++) {
        int ls = l - (Kc - 1) + j;
        if (ls >= 0)
            acc += ln[((size_t)b0 * Ln + ls) * Dn + d] * cw[d * Kc + j];
    }
    u[idx] = acc;
}

// ---------------------------------------------------------------------------
// mma.sync bf16 split GEMM: pre = (x*r) @ Wih^T * s + b
// D = Ahi*Bhi + Ahi*Blo + Alo*Bhi  (fp32 acc).
// CTA: 128M rows, loop 4 N-tiles of 64. 8 warps = 4M x 2N, warp tile 32x32.
// smem row-major bf16, stride 264 (conflict-free fragment loads).
// ---------------------------------------------------------------------------
#define OFF_AHI 0
#define OFF_ALO (128*SSTRIDE)
#define OFF_BHI (256*SSTRIDE)
#define OFF_BLO (320*SSTRIDE)
#define SM3_ELEMS (384*SSTRIDE)
#define SM3_BYTES (SM3_ELEMS*2)

__global__ __launch_bounds__(256, 1)
void gemm3_kernel(const float* __restrict__ inx, const float* __restrict__ Wih,
                  const float* __restrict__ rv, const float* __restrict__ sv,
                  const float* __restrict__ bv, float* __restrict__ pre, int layer0)
{
    extern __shared__ __align__(16) __nv_bfloat16 sm[];
    int tid = threadIdx.x;
    int wid = tid >> 5;
    int lane = tid & 31;
    int bm = blockIdx.x;                 // 512 M-tiles of 128 rows

    int eT = (bm >> 1) & 7;              // ensemble index for this tile
    const float* rrow = rv + (size_t)eT * 256;

    // ---- Convert + split A: 128 rows x 256 k (once) -------------------------
    {
        int row = tid >> 1;
        int kh  = (tid & 1) * 128;
        int rowA = bm * 128 + row;
        size_t srcRow = layer0 ? ((size_t)(rowA >> 11) * 256 + (rowA & 255))
                               : (size_t)rowA;
        const float* arow = inx + srcRow * 256 + kh;
        const float* rr   = rrow + kh;
        __nv_bfloat16* ahi = sm + OFF_AHI + row * SSTRIDE + kh;
        __nv_bfloat16* alo = sm + OFF_ALO + row * SSTRIDE + kh;
        #pragma unroll
        for (int g = 0; g < 32; g++) {
            float4 av = *(const float4*)(arow + g * 4);
            float4 rv4 = *(const float4*)(rr + g * 4);
            av.x *= rv4.x; av.y *= rv4.y; av.z *= rv4.z; av.w *= rv4.w;
            float vv[4] = {av.x, av.y, av.z, av.w};
            float hi[4], lo[4];
            #pragma unroll
            for (int q = 0; q < 4; q++) {
                __nv_bfloat16 h = __float2bfloat16(vv[q]);
                hi[q] = __bfloat162float(h);
                lo[q] = vv[q] - hi[q];
            }
            *(uint2*)(ahi + g * 4) = make_uint2(pbf2(hi[0], hi[1]), pbf2(hi[2], hi[3]));
            *(uint2*)(alo + g * 4) = make_uint2(pbf2(lo[0], lo[1]), pbf2(lo[2], lo[3]));
        }
    }

    int warp_m = wid & 3;                // 0..3 -> M rows warp_m*32..+32
    int warp_n = wid >> 2;               // 0..1 -> N cols warp_n*32..+32
    int grp = lane >> 2;                 // 0..7
    int tg  = lane & 3;                  // 0..3

    for (int bn = 0; bn < 4; bn++) {
        __syncthreads();   // A ready (bn=0) / previous mma reads done
        // ---- Convert + split B tile: 64 rows(h) x 256 k ----------------------
        {
            int row = tid >> 2;
            int kq  = (tid & 3) * 64;
            const float* brow = Wih + (size_t)(bn * 64 + row) * 256 + kq;
            __nv_bfloat16* bhi = sm + OFF_BHI + row * SSTRIDE + kq;
            __nv_bfloat16* blo = sm + OFF_BLO + row * SSTRIDE + kq;
            #pragma unroll
            for (int g = 0; g < 16; g++) {
                float4 bvv = *(const float4*)(brow + g * 4);
                float vv[4] = {bvv.x, bvv.y, bvv.z, bvv.w};
                float hi[4], lo[4];
                #pragma unroll
                for (int q = 0; q < 4; q++) {
                    __nv_bfloat16 h = __float2bfloat16(vv[q]);
                    hi[q] = __bfloat162float(h);
                    lo[q] = vv[q] - hi[q];
                }
                *(uint2*)(bhi + g * 4) = make_uint2(pbf2(hi[0], hi[1]), pbf2(hi[2], hi[3]));
                *(uint2*)(blo + g * 4) = make_uint2(pbf2(lo[0], lo[1]), pbf2(lo[2], lo[3]));
            }
        }
        __syncthreads();

        // ---- Warp mma loop ---------------------------------------------------
        float acc[2][4][4];
        #pragma unroll
        for (int mt = 0; mt < 2; mt++)
            #pragma unroll
            for (int n8 = 0; n8 < 4; n8++)
                #pragma unroll
                for (int q = 0; q < 4; q++) acc[mt][n8][q] = 0.f;

        #pragma unroll 4
        for (int k0 = 0; k0 < 256; k0 += 16) {
            uint32_t ahi_f[2][4], alo_f[2][4];
            #pragma unroll
            for (int mt = 0; mt < 2; mt++) {
                int r0 = warp_m * 32 + mt * 16 + grp;
                const __nv_bfloat16* pHi = sm + OFF_AHI + r0 * SSTRIDE + k0 + tg * 2;
                const __nv_bfloat16* pLo = sm + OFF_ALO + r0 * SSTRIDE + k0 + tg * 2;
                ahi_f[mt][0] = *(const uint32_t*)(pHi);
                ahi_f[mt][1] = *(const uint32_t*)(pHi + 8 * SSTRIDE);
                ahi_f[mt][2] = *(const uint32_t*)(pHi + 8);
                ahi_f[mt][3] = *(const uint32_t*)(pHi + 8 * SSTRIDE + 8);
                alo_f[mt][0] = *(const uint32_t*)(pLo);
                alo_f[mt][1] = *(const uint32_t*)(pLo + 8 * SSTRIDE);
                alo_f[mt][2] = *(const uint32_t*)(pLo + 8);
                alo_f[mt][3] = *(const uint32_t*)(pLo + 8 * SSTRIDE + 8);
            }
            uint32_t bhi_f[4][2], blo_f[4][2];
            #pragma unroll
            for (int n8 = 0; n8 < 4; n8++) {
                int c0 = warp_n * 32 + n8 * 8 + grp;
                const __nv_bfloat16* pHi = sm + OFF_BHI + c0 * SSTRIDE + k0 + tg * 2;
                const __nv_bfloat16* pLo = sm + OFF_BLO + c0 * SSTRIDE + k0 + tg * 2;
                bhi_f[n8][0] = *(const uint32_t*)(pHi);
                bhi_f[n8][1] = *(const uint32_t*)(pHi + 8);
                blo_f[n8][0] = *(const uint32_t*)(pLo);
                blo_f[n8][1] = *(const uint32_t*)(pLo + 8);
            }
            #pragma unroll
            for (int mt = 0; mt < 2; mt++)
                #pragma unroll
                for (int n8 = 0; n8 < 4; n8++) {
                    MMA_BF16(acc[mt][n8], ahi_f[mt], bhi_f[n8]);
                    MMA_BF16(acc[mt][n8], ahi_f[mt], blo_f[n8]);
                    MMA_BF16(acc[mt][n8], alo_f[mt], bhi_f[n8]);
                }
        }

        // ---- Epilogue: *s + b ------------------------------------------------
        const float* srow = sv + (size_t)eT * 256;
        #pragma unroll
        for (int mt = 0; mt < 2; mt++) {
            int rloc = warp_m * 32 + mt * 16 + grp;
            size_t row0 = (size_t)bm * 128 + rloc;
            #pragma unroll
            for (int n8 = 0; n8 < 4; n8++) {
                int col = bn * 64 + warp_n * 32 + n8 * 8 + tg * 2;
                float s0 = srow[col], s1 = srow[col + 1];
                float b0 = bv[col], b1 = bv[col + 1];
                float2 o0, o1;
                o0.x = acc[mt][n8][0] * s0 + b0;
                o0.y = acc[mt][n8][1] * s1 + b1;
                o1.x = acc[mt][n8][2] * s0 + b0;
                o1.y = acc[mt][n8][3] * s1 + b1;
                *(float2*)(pre + row0 * 256 + col) = o0;
                *(float2*)(pre + (row0 + 8) * 256 + col) = o1;
            }
        }
    }
}

// ---------------------------------------------------------------------------
// Recurrence: 64 clusters x 2 CTAs, 4 chains per cluster (round-3 version,
// proven 368 us/layer). Per-step sync = mbarrier handshake; pre load issued
// at top-of-step BEFORE the wait (consumed only at the reduce).
// ---------------------------------------------------------------------------
__device__ __forceinline__ void mbar_wait_cluster(uint32_t mbar, uint32_t parity)
{
    asm volatile(
        "{\n\t"
        ".reg .pred P1;\n\t"
        "WL_%=:\n\t"
        "mbarrier.try_wait.parity.acquire.cluster.shared::cta.b64 P1, [%0], %1;\n\t"
        "@P1 bra.uni WD_%=;\n\t"
        "bra.uni WL_%=;\n\t"
        "WD_%=:\n\t"
        "}" :: "r"(mbar), "r"(parity) : "memory");
}

__global__ __launch_bounds__(256, 1) __cluster_dims__(2, 1, 1)
void rec_kernel(const float* __restrict__ pre, const float* __restrict__ Whh,
                float* __restrict__ yout, float* __restrict__ hlast)
{
    int q = blockIdx.x;
    int c = blockIdx.y;
    int tid = threadIdx.x;
    int tz = tid >> 5;
    int tx = tid & 31;

    float w[4][32];
    #pragma unroll
    for (int a = 0; a < 4; a++) {
        const float* wr = Whh + (size_t)(q * 128 + tx * 4 + a) * Hn + tz * 32;
        #pragma unroll
        for (int j4 = 0; j4 < 8; j4++) {
            float4 v = *(const float4*)(wr + j4 * 4);
            w[a][j4 * 4 + 0] = v.x;
            w[a][j4 * 4 + 1] = v.y;
            w[a][j4 * 4 + 2] = v.z;
            w[a][j4 * 4 + 3] = v.w;
        }
    }

    __shared__ __align__(16) float hbuf[2][4][256];
    __shared__ __align__(16) float part[32][128];
    __shared__ __align__(8) unsigned long long mbar_s;

    for (int i = tid; i < 4 * 256; i += 256) ((float*)hbuf[0])[i] = 0.f;
    if (tid == 0) {
        uint32_t mb = s2u(&mbar_s);
        asm volatile("mbarrier.init.shared.b64 [%0], 256;" :: "r"(mb) : "memory");
    }
    __syncthreads();
    asm volatile("barrier.cluster.arrive.aligned;\n\t"
                 "barrier.cluster.wait.aligned;" ::: "memory");

    int rk = tid & 127;
    int mh = tid >> 7;
    int m0 = mh * 2, m1 = m0 + 1;
    int kg = q * 128 + rk;
    size_t be0 = (size_t)c * 4;

    uint32_t my_mbar = s2u(&mbar_s);
    uint32_t peer_mbar;
    asm("mapa.shared::cluster.u32 %0, %1, %2;" : "=r"(peer_mbar)
        : "r"(my_mbar), "r"(q ^ 1));

    uint32_t pa0[2], pa1[2];
    #pragma unroll
    for (int p = 0; p < 2; p++) {
        uint32_t a0 = s2u(&hbuf[p][m0][kg]);
        uint32_t a1 = s2u(&hbuf[p][m1][kg]);
        asm("mapa.shared::cluster.u32 %0, %1, %2;" : "=r"(pa0[p]) : "r"(a0), "r"(q ^ 1));
        asm("mapa.shared::cluster.u32 %0, %1, %2;" : "=r"(pa1[p]) : "r"(a1), "r"(q ^ 1));
    }

    const float* pre0 = pre + ((be0 + m0) * Ln) * Hn + kg;
    const float* pre1 = pre + ((be0 + m1) * Ln) * Hn + kg;
    float* y0 = yout + ((be0 + m0) * Ln) * Hn + kg;
    float* y1 = yout + ((be0 + m1) * Ln) * Hn + kg;

    int pq = 0;
    unsigned int ph = 0;
    for (int t = 0; t < Ln; t++) {
        float pv0 = pre0[t * Hn];
        float pv1 = pre1[t * Hn];

        if (t > 0) {
            mbar_wait_cluster(my_mbar, ph);
            ph ^= 1u;
        }

        float acc[4][4];
        #pragma unroll
        for (int m = 0; m < 4; m++)
            #pragma unroll
            for (int a = 0; a < 4; a++) acc[m][a] = 0.f;

        #pragma unroll
        for (int j4 = 0; j4 < 8; j4++) {
            float4 h0 = *(const float4*)&hbuf[pq][0][tz * 32 + j4 * 4];
            float4 h1 = *(const float4*)&hbuf[pq][1][tz * 32 + j4 * 4];
            float4 h2 = *(const float4*)&hbuf[pq][2][tz * 32 + j4 * 4];
            float4 h3 = *(const float4*)&hbuf[pq][3][tz * 32 + j4 * 4];
            float hv0[4] = {h0.x, h0.y, h0.z, h0.w};
            float hv1[4] = {h1.x, h1.y, h1.z, h1.w};
            float hv2[4] = {h2.x, h2.y, h2.z, h2.w};
            float hv3[4] = {h3.x, h3.y, h3.z, h3.w};
            #pragma unroll
            for (int jj = 0; jj < 4; jj++) {
                int j = j4 * 4 + jj;
                #pragma unroll
                for (int a = 0; a < 4; a++) {
                    acc[0][a] += w[a][j] * hv0[jj];
                    acc[1][a] += w[a][j] * hv1[jj];
                    acc[2][a] += w[a][j] * hv2[jj];
                    acc[3][a] += w[a][j] * hv3[jj];
                }
            }
        }
        #pragma unroll
        for (int m = 0; m < 4; m++)
            *(float4*)&part[tz * 4 + m][tx * 4] =
                make_float4(acc[m][0], acc[m][1], acc[m][2], acc[m][3]);
        __syncthreads();

        float s0 = pv0, s1 = pv1;
        #pragma unroll
        for (int z = 0; z < 8; z++) {
            s0 += part[z * 4 + m0][rk];
            s1 += part[z * 4 + m1][rk];
        }
        float h0n = fast_tanh(s0);
        float h1n = fast_tanh(s1);

        y0[t * Hn] = h0n;
        y1[t * Hn] = h1n;

        int np = pq ^ 1;
        hbuf[np][m0][kg] = h0n;
        hbuf[np][m1][kg] = h1n;

        if (t < Ln - 1) {
            asm volatile("st.shared::cluster.f32 [%0], %1;" :: "r"(pa0[np]), "f"(h0n));
            asm volatile("st.shared::cluster.f32 [%0], %1;" :: "r"(pa1[np]), "f"(h1n));
            asm volatile("mbarrier.arrive.release.cluster.shared::cluster.b64 _, [%0];"
                         :: "r"(peer_mbar) : "memory");
        }

        if (hlast != nullptr && t == Ln - 1) {
            hlast[(be0 + m0) * Hn + kg] = h0n;
            hlast[(be0 + m1) * Hn + kg] = h1n;
        }

        __syncthreads();
        pq = np;
    }
}

// ---------------------------------------------------------------------------
// Launch
// ---------------------------------------------------------------------------
extern "C" void kernel_launch(void* const* d_in, const int* in_sizes, int n_in,
                              void* d_out, int out_size)
{
    (void)in_sizes; (void)n_in;
    const float* x     = (const float*)d_in[0];
    const float* convw = (const float*)d_in[1];
    const float* convb = (const float*)d_in[2];
    const float* lng   = (const float*)d_in[3];
    const float* lnb   = (const float*)d_in[4];
    const float* Wih   = (const float*)d_in[5];
    const float* Whh   = (const float*)d_in[6];
    const float* rr    = (const float*)d_in[7];
    const float* ss    = (const float*)d_in[8];
    const float* bb    = (const float*)d_in[9];

    float* out = (float*)d_out;
    size_t h_elems = (size_t)Bn * En * Ln * Hn;
    float* hlast = nullptr;
    if ((size_t)out_size >= h_elems + (size_t)Bn * En * Hn)
        hlast = out + h_elems;

    float *p_ln, *p_u, *p_y, *p_pre;
    cudaGetSymbolAddress((void**)&p_ln, g_ln);
    cudaGetSymbolAddress((void**)&p_u, g_u);
    cudaGetSymbolAddress((void**)&p_y, g_y);
    cudaGetSymbolAddress((void**)&p_pre, g_pre);

    static int smem_set = 0;
    if (!smem_set) {
        cudaFuncSetAttribute(gemm3_kernel,
                             cudaFuncAttributeMaxDynamicSharedMemorySize, SM3_BYTES);
        smem_set = 1;
    }

    ln_kernel<<<Bn * Ln, 256>>>(x, lng, lnb, p_ln);
    conv_kernel<<<(Bn * Ln * Dn) / 256, 256>>>(p_ln, convw, convb, p_u);

    for (int i = 0; i < NLn; i++) {
        const float* inx = (i == 0) ? p_u : p_y;
        gemm3_kernel<<<MROWS / 128, Hn / 64 == 4 ? 256 : 256, SM3_BYTES>>>(
            inx,
            Wih + (size_t)i * Hn * Dn,
            rr + (size_t)i * En * Dn,
            ss + (size_t)i * En * Hn,
            bb + (size_t)i * Hn,
            p_pre, (i == 0) ? 1 : 0);

        float* yo = (i == NLn - 1) ? out : p_y;
        rec_kernel<<<dim3(2, 64), 256>>>(
            p_pre,
            Whh + (size_t)i * Hn * Hn,
            yo,
            (i == NLn - 1) ? hlast : (float*)nullptr);
    }
}

// round 15
// speedup vs baseline: 1.5434x; 1.5434x over previous
#include <cuda_runtime.h>
#include <cuda_bf16.h>
#include <cstdint>

// Problem constants
#define Bn 32
#define Ln 256
#define Dn 256
#define Hn 256
#define En 8
#define NLn 4
#define Kc 4
#define MROWS (Bn*En*Ln)     // 65536

#define SSTRIDE 264          // bf16 elems per smem row (pad: stride%32banks=4)

__device__ __forceinline__ float fast_tanh(float x)
{
    float y;
    asm("tanh.approx.f32 %0, %1;" : "=f"(y) : "f"(x));
    return y;
}

__device__ __forceinline__ uint32_t s2u(const void* p)
{
    uint32_t a;
    asm("{ .reg .u64 t; cvta.to.shared.u64 t, %1; cvt.u32.u64 %0, t; }"
        : "=r"(a) : "l"(p));
    return a;
}

// pack two fp32 -> bf16x2 (lo in low half)
__device__ __forceinline__ unsigned int pbf2(float lo, float hi)
{
    unsigned int r;
    asm("cvt.rn.bf16x2.f32 %0, %1, %2;" : "=r"(r) : "f"(hi), "f"(lo));
    return r;
}

#define MMA_BF16(c, a, b) \
    asm volatile( \
        "mma.sync.aligned.m16n8k16.row.col.f32.bf16.bf16.f32 " \
        "{%0,%1,%2,%3}, {%4,%5,%6,%7}, {%8,%9}, {%0,%1,%2,%3};" \
        : "+f"((c)[0]), "+f"((c)[1]), "+f"((c)[2]), "+f"((c)[3]) \
        : "r"((a)[0]), "r"((a)[1]), "r"((a)[2]), "r"((a)[3]), \
          "r"((b)[0]), "r"((b)[1]))

// Scratch (device globals - no allocation allowed)
__device__ float g_ln[Bn*Ln*Dn];                 // 8 MB
__device__ float g_u[Bn*Ln*Dn];                  // 8 MB
__device__ float g_y[(size_t)Bn*En*Ln*Hn];       // 64 MB
__device__ float g_pre[(size_t)Bn*En*Ln*Hn];     // 64 MB

// ---------------------------------------------------------------------------
// LayerNorm
// ---------------------------------------------------------------------------
__global__ void ln_kernel(const float* __restrict__ x, const float* __restrict__ g,
                          const float* __restrict__ bb, float* __restrict__ out)
{
    int token = blockIdx.x;
    int t = threadIdx.x;
    __shared__ float red[8];
    __shared__ float meanv, rstdv;

    float v = x[(size_t)token * Dn + t];

    float s = v;
    #pragma unroll
    for (int o = 16; o > 0; o >>= 1) s += __shfl_xor_sync(0xffffffffu, s, o);
    if ((t & 31) == 0) red[t >> 5] = s;
    __syncthreads();
    if (t == 0) {
        float m = 0.f;
        #pragma unroll
        for (int i = 0; i < 8; i++) m += red[i];
        meanv = m * (1.0f / Dn);
    }
    __syncthreads();

    float d = v - meanv;
    float sq = d * d;
    #pragma unroll
    for (int o = 16; o > 0; o >>= 1) sq += __shfl_xor_sync(0xffffffffu, sq, o);
    if ((t & 31) == 0) red[t >> 5] = sq;
    __syncthreads();
    if (t == 0) {
        float vv = 0.f;
        #pragma unroll
        for (int i = 0; i < 8; i++) vv += red[i];
        rstdv = rsqrtf(vv * (1.0f / Dn) + 1e-5f);
    }
    __syncthreads();

    out[(size_t)token * Dn + t] = d * rstdv * g[t] + bb[t];
}

// ---------------------------------------------------------------------------
// Depthwise causal conv1d (K=4, left pad 3) + bias
// ---------------------------------------------------------------------------
__global__ void conv_kernel(const float* __restrict__ ln, const float* __restrict__ cw,
                            const float* __restrict__ cb, float* __restrict__ u)
{
    int idx = blockIdx.x * 256 + threadIdx.x;
    int d  = idx & 255;
    int l  = (idx >> 8) & 255;
    int b0 = idx >> 16;
    float acc = cb[d];
    #pragma unroll
    for (int j = 0; j < Kc; j++) {
        int ls = l - (Kc - 1) + j;
        if (ls >= 0)
            acc += ln[((size_t)b0 * Ln + ls) * Dn + d] * cw[d * Kc + j];
    }
    u[idx] = acc;
}

// ---------------------------------------------------------------------------
// mma.sync bf16 split GEMM (round-5, proven): pre = (x*r) @ Wih^T * s + b
// ---------------------------------------------------------------------------
#define OFF_AHI 0
#define OFF_ALO (128*SSTRIDE)
#define OFF_BHI (256*SSTRIDE)
#define OFF_BLO (320*SSTRIDE)
#define SM3_ELEMS (384*SSTRIDE)
#define SM3_BYTES (SM3_ELEMS*2)

__global__ __launch_bounds__(256, 1)
void gemm3_kernel(const float* __restrict__ inx, const float* __restrict__ Wih,
                  const float* __restrict__ rv, const float* __restrict__ sv,
                  const float* __restrict__ bv, float* __restrict__ pre, int layer0)
{
    extern __shared__ __align__(16) __nv_bfloat16 sm[];
    int tid = threadIdx.x;
    int wid = tid >> 5;
    int lane = tid & 31;
    int bm = blockIdx.x;                 // 512 M-tiles of 128 rows

    int eT = (bm >> 1) & 7;              // ensemble index for this tile
    const float* rrow = rv + (size_t)eT * 256;

    // ---- Convert + split A: 128 rows x 256 k (once) -------------------------
    {
        int row = tid >> 1;
        int kh  = (tid & 1) * 128;
        int rowA = bm * 128 + row;
        size_t srcRow = layer0 ? ((size_t)(rowA >> 11) * 256 + (rowA & 255))
                               : (size_t)rowA;
        const float* arow = inx + srcRow * 256 + kh;
        const float* rr   = rrow + kh;
        __nv_bfloat16* ahi = sm + OFF_AHI + row * SSTRIDE + kh;
        __nv_bfloat16* alo = sm + OFF_ALO + row * SSTRIDE + kh;
        #pragma unroll
        for (int g = 0; g < 32; g++) {
            float4 av = *(const float4*)(arow + g * 4);
            float4 rv4 = *(const float4*)(rr + g * 4);
            av.x *= rv4.x; av.y *= rv4.y; av.z *= rv4.z; av.w *= rv4.w;
            float vv[4] = {av.x, av.y, av.z, av.w};
            float hi[4], lo[4];
            #pragma unroll
            for (int q = 0; q < 4; q++) {
                __nv_bfloat16 h = __float2bfloat16(vv[q]);
                hi[q] = __bfloat162float(h);
                lo[q] = vv[q] - hi[q];
            }
            *(uint2*)(ahi + g * 4) = make_uint2(pbf2(hi[0], hi[1]), pbf2(hi[2], hi[3]));
            *(uint2*)(alo + g * 4) = make_uint2(pbf2(lo[0], lo[1]), pbf2(lo[2], lo[3]));
        }
    }

    int warp_m = wid & 3;                // 0..3 -> M rows warp_m*32..+32
    int warp_n = wid >> 2;               // 0..1 -> N cols warp_n*32..+32
    int grp = lane >> 2;                 // 0..7
    int tg  = lane & 3;                  // 0..3

    for (int bn = 0; bn < 4; bn++) {
        __syncthreads();   // A ready (bn=0) / previous mma reads done
        // ---- Convert + split B tile: 64 rows(h) x 256 k ----------------------
        {
            int row = tid >> 2;
            int kq  = (tid & 3) * 64;
            const float* brow = Wih + (size_t)(bn * 64 + row) * 256 + kq;
            __nv_bfloat16* bhi = sm + OFF_BHI + row * SSTRIDE + kq;
            __nv_bfloat16* blo = sm + OFF_BLO + row * SSTRIDE + kq;
            #pragma unroll
            for (int g = 0; g < 16; g++) {
                float4 bvv = *(const float4*)(brow + g * 4);
                float vv[4] = {bvv.x, bvv.y, bvv.z, bvv.w};
                float hi[4], lo[4];
                #pragma unroll
                for (int q = 0; q < 4; q++) {
                    __nv_bfloat16 h = __float2bfloat16(vv[q]);
                    hi[q] = __bfloat162float(h);
                    lo[q] = vv[q] - hi[q];
                }
                *(uint2*)(bhi + g * 4) = make_uint2(pbf2(hi[0], hi[1]), pbf2(hi[2], hi[3]));
                *(uint2*)(blo + g * 4) = make_uint2(pbf2(lo[0], lo[1]), pbf2(lo[2], lo[3]));
            }
        }
        __syncthreads();

        // ---- Warp mma loop ---------------------------------------------------
        float acc[2][4][4];
        #pragma unroll
        for (int mt = 0; mt < 2; mt++)
            #pragma unroll
            for (int n8 = 0; n8 < 4; n8++)
                #pragma unroll
                for (int q = 0; q < 4; q++) acc[mt][n8][q] = 0.f;

        #pragma unroll 4
        for (int k0 = 0; k0 < 256; k0 += 16) {
            uint32_t ahi_f[2][4], alo_f[2][4];
            #pragma unroll
            for (int mt = 0; mt < 2; mt++) {
                int r0 = warp_m * 32 + mt * 16 + grp;
                const __nv_bfloat16* pHi = sm + OFF_AHI + r0 * SSTRIDE + k0 + tg * 2;
                const __nv_bfloat16* pLo = sm + OFF_ALO + r0 * SSTRIDE + k0 + tg * 2;
                ahi_f[mt][0] = *(const uint32_t*)(pHi);
                ahi_f[mt][1] = *(const uint32_t*)(pHi + 8 * SSTRIDE);
                ahi_f[mt][2] = *(const uint32_t*)(pHi + 8);
                ahi_f[mt][3] = *(const uint32_t*)(pHi + 8 * SSTRIDE + 8);
                alo_f[mt][0] = *(const uint32_t*)(pLo);
                alo_f[mt][1] = *(const uint32_t*)(pLo + 8 * SSTRIDE);
                alo_f[mt][2] = *(const uint32_t*)(pLo + 8);
                alo_f[mt][3] = *(const uint32_t*)(pLo + 8 * SSTRIDE + 8);
            }
            uint32_t bhi_f[4][2], blo_f[4][2];
            #pragma unroll
            for (int n8 = 0; n8 < 4; n8++) {
                int c0 = warp_n * 32 + n8 * 8 + grp;
                const __nv_bfloat16* pHi = sm + OFF_BHI + c0 * SSTRIDE + k0 + tg * 2;
                const __nv_bfloat16* pLo = sm + OFF_BLO + c0 * SSTRIDE + k0 + tg * 2;
                bhi_f[n8][0] = *(const uint32_t*)(pHi);
                bhi_f[n8][1] = *(const uint32_t*)(pHi + 8);
                blo_f[n8][0] = *(const uint32_t*)(pLo);
                blo_f[n8][1] = *(const uint32_t*)(pLo + 8);
            }
            #pragma unroll
            for (int mt = 0; mt < 2; mt++)
                #pragma unroll
                for (int n8 = 0; n8 < 4; n8++) {
                    MMA_BF16(acc[mt][n8], ahi_f[mt], bhi_f[n8]);
                    MMA_BF16(acc[mt][n8], ahi_f[mt], blo_f[n8]);
                    MMA_BF16(acc[mt][n8], alo_f[mt], bhi_f[n8]);
                }
        }

        // ---- Epilogue: *s + b ------------------------------------------------
        const float* srow = sv + (size_t)eT * 256;
        #pragma unroll
        for (int mt = 0; mt < 2; mt++) {
            int rloc = warp_m * 32 + mt * 16 + grp;
            size_t row0 = (size_t)bm * 128 + rloc;
            #pragma unroll
            for (int n8 = 0; n8 < 4; n8++) {
                int col = bn * 64 + warp_n * 32 + n8 * 8 + tg * 2;
                float s0 = srow[col], s1 = srow[col + 1];
                float b0 = bv[col], b1 = bv[col + 1];
                float2 o0, o1;
                o0.x = acc[mt][n8][0] * s0 + b0;
                o0.y = acc[mt][n8][1] * s1 + b1;
                o1.x = acc[mt][n8][2] * s0 + b0;
                o1.y = acc[mt][n8][3] * s1 + b1;
                *(float2*)(pre + row0 * 256 + col) = o0;
                *(float2*)(pre + (row0 + 8) * 256 + col) = o1;
            }
        }
    }
}

// ---------------------------------------------------------------------------
// Recurrence: round-3/5 skeleton with ONE change: warps whose j-slice lies
// in the LOCALLY-produced half of h (tz>>2 == q) skip the cluster mbarrier
// wait — their inputs are ordered by the end-of-step __syncthreads. Only the
// 4 peer-half warps (one per SMSP) wait, so each SMSP starts FFMA work
// immediately while the peer's DSMEM delivery (~330 cyc) is in flight.
// Arrive pattern unchanged (all 256 threads arrive on peer's 256-count mbar).
// ---------------------------------------------------------------------------
__device__ __forceinline__ void mbar_wait_cluster(uint32_t mbar, uint32_t parity)
{
    asm volatile(
        "{\n\t"
        ".reg .pred P1;\n\t"
        "WL_%=:\n\t"
        "mbarrier.try_wait.parity.acquire.cluster.shared::cta.b64 P1, [%0], %1;\n\t"
        "@P1 bra.uni WD_%=;\n\t"
        "bra.uni WL_%=;\n\t"
        "WD_%=:\n\t"
        "}" :: "r"(mbar), "r"(parity) : "memory");
}

__global__ __launch_bounds__(256, 1) __cluster_dims__(2, 1, 1)
void rec_kernel(const float* __restrict__ pre, const float* __restrict__ Whh,
                float* __restrict__ yout, float* __restrict__ hlast)
{
    int q = blockIdx.x;
    int c = blockIdx.y;
    int tid = threadIdx.x;
    int tz = tid >> 5;
    int tx = tid & 31;

    float w[4][32];
    #pragma unroll
    for (int a = 0; a < 4; a++) {
        const float* wr = Whh + (size_t)(q * 128 + tx * 4 + a) * Hn + tz * 32;
        #pragma unroll
        for (int j4 = 0; j4 < 8; j4++) {
            float4 v = *(const float4*)(wr + j4 * 4);
            w[a][j4 * 4 + 0] = v.x;
            w[a][j4 * 4 + 1] = v.y;
            w[a][j4 * 4 + 2] = v.z;
            w[a][j4 * 4 + 3] = v.w;
        }
    }

    __shared__ __align__(16) float hbuf[2][4][256];
    __shared__ __align__(16) float part[32][128];
    __shared__ __align__(8) unsigned long long mbar_s;

    for (int i = tid; i < 4 * 256; i += 256) ((float*)hbuf[0])[i] = 0.f;
    if (tid == 0) {
        uint32_t mb = s2u(&mbar_s);
        asm volatile("mbarrier.init.shared.b64 [%0], 256;" :: "r"(mb) : "memory");
    }
    __syncthreads();
    asm volatile("barrier.cluster.arrive.aligned;\n\t"
                 "barrier.cluster.wait.aligned;" ::: "memory");

    int rk = tid & 127;
    int mh = tid >> 7;
    int m0 = mh * 2, m1 = m0 + 1;
    int kg = q * 128 + rk;
    size_t be0 = (size_t)c * 4;

    // local-half warp: j-slice produced by THIS CTA -> no cluster wait needed
    int early = ((tz >> 2) == q);

    uint32_t my_mbar = s2u(&mbar_s);
    uint32_t peer_mbar;
    asm("mapa.shared::cluster.u32 %0, %1, %2;" : "=r"(peer_mbar)
        : "r"(my_mbar), "r"(q ^ 1));

    uint32_t pa0[2], pa1[2];
    #pragma unroll
    for (int p = 0; p < 2; p++) {
        uint32_t a0 = s2u(&hbuf[p][m0][kg]);
        uint32_t a1 = s2u(&hbuf[p][m1][kg]);
        asm("mapa.shared::cluster.u32 %0, %1, %2;" : "=r"(pa0[p]) : "r"(a0), "r"(q ^ 1));
        asm("mapa.shared::cluster.u32 %0, %1, %2;" : "=r"(pa1[p]) : "r"(a1), "r"(q ^ 1));
    }

    const float* pre0 = pre + ((be0 + m0) * Ln) * Hn + kg;
    const float* pre1 = pre + ((be0 + m1) * Ln) * Hn + kg;
    float* y0 = yout + ((be0 + m0) * Ln) * Hn + kg;
    float* y1 = yout + ((be0 + m1) * Ln) * Hn + kg;

    int pq = 0;
    unsigned int ph = 0;
    for (int t = 0; t < Ln; t++) {
        float pv0 = pre0[t * Hn];
        float pv1 = pre1[t * Hn];

        if (t > 0) {
            if (!early) mbar_wait_cluster(my_mbar, ph);
            ph ^= 1u;
        }

        float acc[4][4];
        #pragma unroll
        for (int m = 0; m < 4; m++)
            #pragma unroll
            for (int a = 0; a < 4; a++) acc[m][a] = 0.f;

        #pragma unroll
        for (int j4 = 0; j4 < 8; j4++) {
            float4 h0 = *(const float4*)&hbuf[pq][0][tz * 32 + j4 * 4];
            float4 h1 = *(const float4*)&hbuf[pq][1][tz * 32 + j4 * 4];
            float4 h2 = *(const float4*)&hbuf[pq][2][tz * 32 + j4 * 4];
            float4 h3 = *(const float4*)&hbuf[pq][3][tz * 32 + j4 * 4];
            float hv0[4] = {h0.x, h0.y, h0.z, h0.w};
            float hv1[4] = {h1.x, h1.y, h1.z, h1.w};
            float hv2[4] = {h2.x, h2.y, h2.z, h2.w};
            float hv3[4] = {h3.x, h3.y, h3.z, h3.w};
            #pragma unroll
            for (int jj = 0; jj < 4; jj++) {
                int j = j4 * 4 + jj;
                #pragma unroll
                for (int a = 0; a < 4; a++) {
                    acc[0][a] += w[a][j] * hv0[jj];
                    acc[1][a] += w[a][j] * hv1[jj];
                    acc[2][a] += w[a][j] * hv2[jj];
                    acc[3][a] += w[a][j] * hv3[jj];
                }
            }
        }
        #pragma unroll
        for (int m = 0; m < 4; m++)
            *(float4*)&part[tz * 4 + m][tx * 4] =
                make_float4(acc[m][0], acc[m][1], acc[m][2], acc[m][3]);
        __syncthreads();

        float s0 = pv0, s1 = pv1;
        #pragma unroll
        for (int z = 0; z < 8; z++) {
            s0 += part[z * 4 + m0][rk];
            s1 += part[z * 4 + m1][rk];
        }
        float h0n = fast_tanh(s0);
        float h1n = fast_tanh(s1);

        y0[t * Hn] = h0n;
        y1[t * Hn] = h1n;

        int np = pq ^ 1;
        hbuf[np][m0][kg] = h0n;
        hbuf[np][m1][kg] = h1n;

        if (t < Ln - 1) {
            asm volatile("st.shared::cluster.f32 [%0], %1;" :: "r"(pa0[np]), "f"(h0n));
            asm volatile("st.shared::cluster.f32 [%0], %1;" :: "r"(pa1[np]), "f"(h1n));
            asm volatile("mbarrier.arrive.release.cluster.shared::cluster.b64 _, [%0];"
                         :: "r"(peer_mbar) : "memory");
        }

        if (hlast != nullptr && t == Ln - 1) {
            hlast[(be0 + m0) * Hn + kg] = h0n;
            hlast[(be0 + m1) * Hn + kg] = h1n;
        }

        __syncthreads();
        pq = np;
    }
}

// ---------------------------------------------------------------------------
// Launch
// ---------------------------------------------------------------------------
extern "C" void kernel_launch(void* const* d_in, const int* in_sizes, int n_in,
                              void* d_out, int out_size)
{
    (void)in_sizes; (void)n_in;
    const float* x     = (const float*)d_in[0];
    const float* convw = (const float*)d_in[1];
    const float* convb = (const float*)d_in[2];
    const float* lng   = (const float*)d_in[3];
    const float* lnb   = (const float*)d_in[4];
    const float* Wih   = (const float*)d_in[5];
    const float* Whh   = (const float*)d_in[6];
    const float* rr    = (const float*)d_in[7];
    const float* ss    = (const float*)d_in[8];
    const float* bb    = (const float*)d_in[9];

    float* out = (float*)d_out;
    size_t h_elems = (size_t)Bn * En * Ln * Hn;
    float* hlast = nullptr;
    if ((size_t)out_size >= h_elems + (size_t)Bn * En * Hn)
        hlast = out + h_elems;

    float *p_ln, *p_u, *p_y, *p_pre;
    cudaGetSymbolAddress((void**)&p_ln, g_ln);
    cudaGetSymbolAddress((void**)&p_u, g_u);
    cudaGetSymbolAddress((void**)&p_y, g_y);
    cudaGetSymbolAddress((void**)&p_pre, g_pre);

    static int smem_set = 0;
    if (!smem_set) {
        cudaFuncSetAttribute(gemm3_kernel,
                             cudaFuncAttributeMaxDynamicSharedMemorySize, SM3_BYTES);
        smem_set = 1;
    }

    ln_kernel<<<Bn * Ln, 256>>>(x, lng, lnb, p_ln);
    conv_kernel<<<(Bn * Ln * Dn) / 256, 256>>>(p_ln, convw, convb, p_u);

    for (int i = 0; i < NLn; i++) {
        const float* inx = (i == 0) ? p_u : p_y;
        gemm3_kernel<<<MROWS / 128, 256, SM3_BYTES>>>(
            inx,
            Wih + (size_t)i * Hn * Dn,
            rr + (size_t)i * En * Dn,
            ss + (size_t)i * En * Hn,
            bb + (size_t)i * Hn,
            p_pre, (i == 0) ? 1 : 0);

        float* yo = (i == NLn - 1) ? out : p_y;
        rec_kernel<<<dim3(2, 64), 256>>>(
            p_pre,
            Whh + (size_t)i * Hn * Hn,
            yo,
            (i == NLn - 1) ? hlast : (float*)nullptr);
    }
}